// round 11
// baseline (speedup 1.0000x reference)
#include <cuda_runtime.h>
#include <math.h>
#include <stdint.h>

#define BATCH     16
#define MEM_DIM   172
#define KPAD      176
#define TOK       4096
#define TIME_DIM  100
#define TPAD      112
#define LEN_TOK   512
#define NROWS     44
#define ASTRIDE   24

#define PROJ_PER_B 32      // proj CTAs per batch (32 tiles of 128 cols)
#define SCAT_PER_B 400     // scat CTAs per batch (16 tiles x 25 runs)
#define CTAS_PER_B (PROJ_PER_B + SCAT_PER_B)

typedef unsigned long long ull;

__device__ __align__(16) float g_res[BATCH * NROWS * TOK];
__device__ int g_cnt[BATCH];

__device__ __forceinline__ ull pack2(float lo, float hi) {
    ull d; asm("mov.b64 %0, {%1, %2};" : "=l"(d) : "f"(lo), "f"(hi)); return d;
}
__device__ __forceinline__ void unpack2(ull v, float& lo, float& hi) {
    asm("mov.b64 {%0, %1}, %2;" : "=f"(lo), "=f"(hi) : "l"(v));
}
__device__ __forceinline__ ull fma2(ull a, ull b, ull c) {
    ull d; asm("fma.rn.f32x2 %0, %1, %2, %3;" : "=l"(d) : "l"(a), "l"(b), "l"(c)); return d;
}
__device__ __forceinline__ ull add2(ull a, ull b) {
    ull d; asm("add.rn.f32x2 %0, %1, %2;" : "=l"(d) : "l"(a), "l"(b)); return d;
}
__device__ __forceinline__ uint32_t s2u(const void* p) {
    return (uint32_t)__cvta_generic_to_shared(p);
}
__device__ __forceinline__ void cp16(uint32_t dst, const void* src) {
    asm volatile("cp.async.cg.shared.global [%0], [%1], 16;" :: "r"(dst), "l"(src));
}
__device__ __forceinline__ void cp_commit() { asm volatile("cp.async.commit_group;"); }
template<int N> __device__ __forceinline__ void cp_wait() {
    asm volatile("cp.async.wait_group %0;" :: "n"(N) : "memory");
}

__device__ __forceinline__ void fill_w(float* buf, const float* W1, const float* W2,
                                       int kbase, int colbase, int cl)
{
#pragma unroll
    for (int j = 0; j < 4; j++) {
        int c   = cl + 128 * j;
        int mat = c >> 8;
        int k   = (c >> 5) & 7;
        int c16 = c & 31;
        int krow = kbase + k; if (krow > MEM_DIM - 1) krow = MEM_DIM - 1;
        const float* src = (mat ? W2 : W1) + (size_t)krow * TOK + colbase + c16 * 4;
        cp16(s2u(buf + k * 256 + mat * 128 + c16 * 4), src);
    }
}

__device__ __forceinline__ void fill_t(float* buf, const float* Wt,
                                       int kbase, int colbase, int cl)
{
#pragma unroll
    for (int j = 0; j < 2; j++) {
        int c   = cl + 128 * j;
        int k   = c >> 5;
        int c16 = c & 31;
        int krow = kbase + k; if (krow > TIME_DIM - 1) krow = TIME_DIM - 1;
        cp16(s2u(buf + k * 128 + c16 * 4), Wt + (size_t)krow * TOK + colbase + c16 * 4);
    }
}

#define ASH_B  (KPAD * ASTRIDE * 4)
#define WB_B   (2 * 2 * 8 * 256 * 4)
#define SMEM_B (ASH_B + WB_B)            // 49664 B -> 4 CTAs/SM

// ---------------------------------------------------------------------------
__global__ void k_init() { if (threadIdx.x < BATCH) g_cnt[threadIdx.x] = 0; }

// ---------------------------------------------------------------------------
// One grid, two roles, interleaved per batch:
//   CTA c: b = c/432, r = c%432. r<32 -> proj tile r; else scat (tile, run).
// Proj publishes g_res rows for (b,tile) then bumps g_cnt[b] (fence+atomic).
// Scat spins until g_cnt[b]==32, then streams stores (no smem use).
// ---------------------------------------------------------------------------
__global__ void __launch_bounds__(256, 4)
k_main(const float* __restrict__ memory,
       const int*   __restrict__ src_nodes,
       const int*   __restrict__ dst_nodes,
       const int*   __restrict__ src_nei,
       const int*   __restrict__ dst_nei,
       const float* __restrict__ timestamps,
       const float* __restrict__ se,
       const float* __restrict__ de,
       const float* __restrict__ W1, const float* __restrict__ b1,
       const float* __restrict__ W2, const float* __restrict__ b2,
       const float* __restrict__ Wt, const float* __restrict__ bt,
       const float* __restrict__ w_time,
       const float* __restrict__ phase,
       float*       __restrict__ out)
{
    extern __shared__ __align__(16) char sraw[];

    const int c   = blockIdx.x;
    const int b   = c / CTAS_PER_B;
    const int r   = c - b * CTAS_PER_B;
    const int tid = threadIdx.x;

    if (r < PROJ_PER_B) {
        // ================= PROJ ROLE =================
        float* Ash = (float*)sraw;
        float* Wb  = (float*)(sraw + ASH_B);
        float* Ten = Wb;
        float* Tw  = Wb + TPAD * ASTRIDE;
        ull*   red = (ull*)sraw;

        const int tile    = r;
        const int cl      = tid & 127;
        const int slice   = tid >> 7;
        const int col     = tile * 128 + cl;
        const int colbase = tile * 128;

        const int kb0 = slice ? 88 : 0;
        float* mbuf = Wb + slice * 4096;
        fill_w(mbuf, W1, W2, kb0, colbase, cl);
        cp_commit();

        for (int i = tid; i < 22 * MEM_DIM; i += 256) {
            int rr = i / MEM_DIM;
            int k  = i - rr * MEM_DIM;
            int node;
            if (rr == 0)       node = src_nodes[b];
            else if (rr < 11)  node = dst_nei[b * 10 + rr - 1];
            else if (rr == 11) node = dst_nodes[b];
            else               node = src_nei[b * 10 + rr - 12];
            int slot = (rr < 11) ? (2 * rr) : (2 * (rr - 11) + 1);
            Ash[k * ASTRIDE + slot] = memory[(size_t)node * MEM_DIM + k];
        }
        if (tid < (KPAD - MEM_DIM) * ASTRIDE)
            Ash[MEM_DIM * ASTRIDE + tid] = 0.f;
        __syncthreads();

        float* resb = g_res + (size_t)b * NROWS * TOK + col;

        // ---- mem projection ----
        {
            ull acc[11];
            const ull bi = pack2(b1[col], b2[col]);
#pragma unroll
            for (int p = 0; p < 11; p++) acc[p] = slice == 0 ? bi : 0ull;

            for (int s = 0; s < 11; s++) {
                if (s + 1 < 11) {
                    fill_w(mbuf + ((s + 1) & 1) * 2048, W1, W2, kb0 + (s + 1) * 8, colbase, cl);
                    cp_commit();
                    cp_wait<1>();
                } else {
                    cp_wait<0>();
                }
                __syncthreads();

                const float* bufc = mbuf + (s & 1) * 2048;
                const int kb = kb0 + s * 8;
#pragma unroll
                for (int j = 0; j < 8; j++) {
                    ull w = pack2(bufc[j * 256 + cl], bufc[j * 256 + 128 + cl]);
                    const float* a = Ash + (kb + j) * ASTRIDE;
#pragma unroll
                    for (int q = 0; q < 5; q++) {
                        ulonglong2 v = *(const ulonglong2*)(a + 4 * q);
                        acc[2 * q]     = fma2(v.x, w, acc[2 * q]);
                        acc[2 * q + 1] = fma2(v.y, w, acc[2 * q + 1]);
                    }
                    acc[10] = fma2(*(const ull*)(a + 20), w, acc[10]);
                }
                __syncthreads();
            }

            const int tb0 = slice ? 56 : 0;
            fill_t(Tw + slice * 2048, Wt, tb0, colbase, cl);
            cp_commit();

            if (slice) {
#pragma unroll
                for (int p = 0; p < 11; p++) red[cl * 11 + p] = acc[p];
            }
            __syncthreads();
            if (slice == 0) {
#pragma unroll
                for (int p = 0; p < 11; p++) {
                    acc[p] = add2(acc[p], red[cl * 11 + p]);
                    float lo, hi; unpack2(acc[p], lo, hi);
                    resb[(size_t)p * TOK]        = lo;
                    resb[(size_t)(11 + p) * TOK] = hi;
                }
            }
        }
        __syncthreads();

        // ---- stage Ten ----
        const float t0v = timestamps[b];
        for (int i = tid; i < TPAD * ASTRIDE; i += 256) {
            int k  = i / ASTRIDE;
            int rr = i - k * ASTRIDE;
            float v = 0.f;
            if (k < TIME_DIM && rr < 21) {
                float delta;
                if (rr == 0)      delta = 0.f;
                else if (rr < 11) delta = t0v - se[b * 10 + rr - 1];
                else              delta = t0v - de[b * 10 + rr - 11];
                v = cosf(delta * w_time[k] + phase[k]);
            }
            Ten[i] = v;
        }
        __syncthreads();

        // ---- time projection ----
        {
            const int tb0 = slice ? 56 : 0;
            float* tbuf = Tw + slice * 2048;

            ull acc[11];
            const float btc = bt[col];
            const ull bi = pack2(btc, btc);
#pragma unroll
            for (int p = 0; p < 11; p++) acc[p] = slice == 0 ? bi : 0ull;

            for (int s = 0; s < 7; s++) {
                if (s + 1 < 7) {
                    fill_t(tbuf + ((s + 1) & 1) * 1024, Wt, tb0 + (s + 1) * 8, colbase, cl);
                    cp_commit();
                    cp_wait<1>();
                } else {
                    cp_wait<0>();
                }
                __syncthreads();

                const float* bufc = tbuf + (s & 1) * 1024;
                const int kb = tb0 + s * 8;
#pragma unroll
                for (int j = 0; j < 8; j++) {
                    float wt = bufc[j * 128 + cl];
                    ull w = pack2(wt, wt);
                    const float* a = Ten + (kb + j) * ASTRIDE;
#pragma unroll
                    for (int q = 0; q < 5; q++) {
                        ulonglong2 v = *(const ulonglong2*)(a + 4 * q);
                        acc[2 * q]     = fma2(v.x, w, acc[2 * q]);
                        acc[2 * q + 1] = fma2(v.y, w, acc[2 * q + 1]);
                    }
                    acc[10] = fma2(*(const ull*)(a + 20), w, acc[10]);
                }
                __syncthreads();
            }

            if (slice) {
#pragma unroll
                for (int p = 0; p < 11; p++) red[cl * 11 + p] = acc[p];
            }
            __syncthreads();
            if (slice == 0) {
#pragma unroll
                for (int p = 0; p < 11; p++) {
                    acc[p] = add2(acc[p], red[cl * 11 + p]);
                    float lo, hi; unpack2(acc[p], lo, hi);
                    resb[(size_t)(22 + 2 * p) * TOK] = lo;
                    resb[(size_t)(23 + 2 * p) * TOK] = hi;
                }
            }
        }

        // ---- publish: all g_res writes for (b,tile) visible, then count ----
        __threadfence();
        __syncthreads();
        if (tid == 0) atomicAdd(&g_cnt[b], 1);

    } else {
        // ================= SCAT ROLE =================
        const int sid  = r - PROJ_PER_B;
        const int tile = sid / 25;
        const int z    = sid - tile * 25;
        const int lane = tid & 63;
        const int sub  = tid >> 6;

        // wait for batch b's 32 proj CTAs
        if (tid == 0) {
            unsigned v;
            while (true) {
                asm volatile("ld.acquire.gpu.global.u32 %0, [%1];"
                             : "=r"(v) : "l"(&g_cnt[b]) : "memory");
                if (v >= PROJ_PER_B) break;
                __nanosleep(200);
            }
        }
        __syncthreads();

        int t0, n, rS, rD, rT;
        if (z < 10)       { t0 = 15 + 21 * z;  n = 21; rS = 0;  rD = 12 + z; rT = 23 + z; }
        else if (z < 20)  { int q = z - 10; t0 = 239 + 21 * q; n = 21; rS = 11; rD = 1 + q; rT = 33 + q; }
        else if (z == 20) { t0 = 0;   n = 15; rS = 0;  rD = 11; rT = 22; }
        else if (z == 21) { t0 = 225; n = 14; rS = 11; rD = 11; rT = 22; }
        else              { t0 = 449 + 21 * (z - 22); n = 21; rS = 0; rD = 11; rT = 22; }

        const float4* gresv = (const float4*)g_res;
        const int vrow = TOK / 4;
        const size_t rbase = (size_t)b * NROWS * vrow + tile * 64 + lane;
        const float4 vs = __ldcg(&gresv[rbase + (size_t)rS * vrow]);   // L2 path (coherent)
        const float4 vd = __ldcg(&gresv[rbase + (size_t)rD * vrow]);
        const float4 vt = __ldcg(&gresv[rbase + (size_t)rT * vrow]);

        float4* outv = (float4*)out;
        const size_t T = (size_t)BATCH * LEN_TOK * vrow;
        const size_t obase = (size_t)(b * LEN_TOK) * vrow + tile * 64 + lane;

        if (z == 20) {
            for (int i = sub; i < n; i += 4) {
                const int t = t0 + i;
                const size_t o = obase + (size_t)t * vrow;
                __stcs(&outv[o],         vs);
                __stcs(&outv[o + T],     (t == 0) ? vd : vs);
                __stcs(&outv[o + 2 * T], vt);
            }
        } else {
            for (int i = sub; i < n; i += 4) {
                const size_t o = obase + (size_t)(t0 + i) * vrow;
                __stcs(&outv[o],         vs);
                __stcs(&outv[o + T],     vd);
                __stcs(&outv[o + 2 * T], vt);
            }
        }
    }
}

// ---------------------------------------------------------------------------
extern "C" void kernel_launch(void* const* d_in, const int* in_sizes, int n_in,
                              void* d_out, int out_size)
{
    const float* memory      = (const float*)d_in[0];
    const int*   src_nodes   = (const int*)  d_in[1];
    const int*   dst_nodes   = (const int*)  d_in[2];
    const int*   src_nei     = (const int*)  d_in[3];
    const int*   dst_nei     = (const int*)  d_in[4];
    const float* timestamps  = (const float*)d_in[5];
    const float* se          = (const float*)d_in[6];
    const float* de          = (const float*)d_in[7];
    const float* W1          = (const float*)d_in[8];
    const float* b1          = (const float*)d_in[9];
    const float* W2          = (const float*)d_in[10];
    const float* b2          = (const float*)d_in[11];
    const float* Wt          = (const float*)d_in[12];
    const float* bt          = (const float*)d_in[13];
    const float* w_time      = (const float*)d_in[14];
    const float* phase       = (const float*)d_in[15];
    float* out = (float*)d_out;

    cudaFuncSetAttribute(k_main, cudaFuncAttributeMaxDynamicSharedMemorySize, SMEM_B);

    k_init<<<1, 32>>>();
    k_main<<<BATCH * CTAS_PER_B, 256, SMEM_B>>>(memory, src_nodes, dst_nodes,
                                                src_nei, dst_nei,
                                                timestamps, se, de,
                                                W1, b1, W2, b2, Wt, bt,
                                                w_time, phase, out);
}

// round 12
// speedup vs baseline: 2.9035x; 2.9035x over previous
#include <cuda_runtime.h>
#include <cuda_bf16.h>
#include <math.h>
#include <stdint.h>

#define BATCH     16
#define MEM_DIM   172
#define TOK       4096
#define TIME_DIM  100
#define LEN_TOK   512
#define NROWS     44

// g_wh/g_wl row layout: [0,176) = W1 (pad rows 0), [176,352) = W2, [352,464) = Wt
#define WROWS     464

__device__ __align__(16) __nv_bfloat16 g_wh[WROWS * TOK];
__device__ __align__(16) __nv_bfloat16 g_wl[WROWS * TOK];
__device__ __align__(16) float g_res[BATCH * NROWS * TOK];

// ---------------------------------------------------------------------------
__device__ __forceinline__ uint32_t s2u(const void* p) {
    return (uint32_t)__cvta_generic_to_shared(p);
}
__device__ __forceinline__ void cp16(uint32_t dst, const void* src) {
    asm volatile("cp.async.cg.shared.global [%0], [%1], 16;" :: "r"(dst), "l"(src));
}
__device__ __forceinline__ void cp_commit() { asm volatile("cp.async.commit_group;"); }
template<int N> __device__ __forceinline__ void cp_wait() {
    asm volatile("cp.async.wait_group %0;" :: "n"(N) : "memory");
}
__device__ __forceinline__ void mma_bf16(float& d0, float& d1, float& d2, float& d3,
                                         uint32_t a0, uint32_t a1, uint32_t a2, uint32_t a3,
                                         uint32_t b0, uint32_t b1)
{
    asm volatile(
        "mma.sync.aligned.m16n8k16.row.col.f32.bf16.bf16.f32 "
        "{%0,%1,%2,%3}, {%4,%5,%6,%7}, {%8,%9}, {%0,%1,%2,%3};"
        : "+f"(d0), "+f"(d1), "+f"(d2), "+f"(d3)
        : "r"(a0), "r"(a1), "r"(a2), "r"(a3), "r"(b0), "r"(b1));
}
__device__ __forceinline__ void ldsm_x4(uint32_t& r0, uint32_t& r1, uint32_t& r2,
                                        uint32_t& r3, uint32_t addr) {
    asm volatile("ldmatrix.sync.aligned.m8n8.x4.shared.b16 {%0,%1,%2,%3}, [%4];"
                 : "=r"(r0), "=r"(r1), "=r"(r2), "=r"(r3) : "r"(addr));
}
__device__ __forceinline__ void ldsm_x2t(uint32_t& r0, uint32_t& r1, uint32_t addr) {
    asm volatile("ldmatrix.sync.aligned.m8n8.x2.trans.shared.b16 {%0,%1}, [%2];"
                 : "=r"(r0), "=r"(r1) : "r"(addr));
}

// ---------------------------------------------------------------------------
// Prep: split W1/W2/Wt into bf16 hi/lo, padded K rows zeroed.
// ---------------------------------------------------------------------------
__global__ void __launch_bounds__(256)
k_prep(const float* __restrict__ W1, const float* __restrict__ W2,
       const float* __restrict__ Wt)
{
    int i = blockIdx.x * 256 + threadIdx.x;
    if (i >= WROWS * TOK) return;
    int row = i >> 12;
    int col = i & 4095;
    float w = 0.f;
    if (row < 176)      { if (row < 172)       w = W1[row * TOK + col]; }
    else if (row < 352) { int k = row - 176; if (k < 172) w = W2[k * TOK + col]; }
    else                { int k = row - 352; if (k < 100) w = Wt[k * TOK + col]; }
    __nv_bfloat16 h = __float2bfloat16(w);
    g_wh[i] = h;
    g_wl[i] = __float2bfloat16(w - __bfloat162float(h));
}

// ---------------------------------------------------------------------------
// Proj smem layout (bytes):
//   [0, 24064)  A region: G1/G2: A1h@0, A1l@5888, A2h@11776, A2l@17664 (16x184 bf16, 368B rows)
//               G3 (reuse): Th@0, Tl@7680 (32x120 bf16, 240B rows)
//   [24064, +2*16896)  two W stages: each = [hi 16x528B][lo 16x528B]
// ---------------------------------------------------------------------------
#define A_REGION_B 24064
#define WS_ROW_B   528
#define WSTG_B     (2 * 16 * WS_ROW_B)           // 16896
#define SMEMP_B    (A_REGION_B + 2 * WSTG_B)     // 57856

__device__ __forceinline__ void fill_wstage(char* stg, int krow0, int col0, int tid)
{
#pragma unroll
    for (int j = 0; j < 4; j++) {
        int c   = tid + 256 * j;            // 0..1023
        int mat = c >> 9;                   // 0 = hi, 1 = lo
        int r   = (c >> 5) & 15;
        int c16 = c & 31;
        const __nv_bfloat16* src = (mat ? g_wl : g_wh)
                                 + (size_t)(krow0 + r) * TOK + col0 + c16 * 8;
        cp16(s2u(stg + mat * (16 * WS_ROW_B) + r * WS_ROW_B + c16 * 16), src);
    }
}

// One GEMM: MT m16-tiles, NSTEP k16-steps. 3-product bf16 compensated.
template<int MT, int NSTEP>
__device__ __forceinline__ void run_gemm(
    char* stg0, char* stg1,
    uint32_t aH, uint32_t aL, int astride_b,
    int wrow0, int col0, int b, int orow0, int nvalid,
    const float* __restrict__ bias, int tid)
{
    const int lane = tid & 31;
    const int wid  = tid >> 5;
    const int n0   = wid * 32;              // 32 cols per warp (4 n8 tiles)
    const int g    = lane >> 2;
    const int tg   = lane & 3;
    const int arow = lane & 15;
    const int acol = (lane >> 4) << 3;      // 0 or 8
    const int brow = lane & 15;

    float acc[MT][4][4];
#pragma unroll
    for (int mt = 0; mt < MT; mt++)
#pragma unroll
        for (int j = 0; j < 4; j++)
#pragma unroll
            for (int q = 0; q < 4; q++) acc[mt][j][q] = 0.f;

    fill_wstage(stg0, wrow0, col0, tid);
    cp_commit();

    for (int s = 0; s < NSTEP; s++) {
        if (s + 1 < NSTEP) {
            fill_wstage((s & 1) ? stg0 : stg1, wrow0 + (s + 1) * 16, col0, tid);
            cp_commit();
            cp_wait<1>();
        } else {
            cp_wait<0>();
        }
        __syncthreads();

        char* st = (s & 1) ? stg1 : stg0;
        const uint32_t st_s = s2u(st);
        const int k0 = s * 16;

        uint32_t bh[4][2], bl[4][2];
#pragma unroll
        for (int j = 0; j < 4; j++) {
            uint32_t baddr = st_s + brow * WS_ROW_B + (n0 + j * 8) * 2;
            ldsm_x2t(bh[j][0], bh[j][1], baddr);
            ldsm_x2t(bl[j][0], bl[j][1], baddr + 16 * WS_ROW_B);
        }
#pragma unroll
        for (int mt = 0; mt < MT; mt++) {
            uint32_t ah0, ah1, ah2, ah3, al0, al1, al2, al3;
            ldsm_x4(ah0, ah1, ah2, ah3,
                    aH + (mt * 16 + arow) * astride_b + (k0 + acol) * 2);
            ldsm_x4(al0, al1, al2, al3,
                    aL + (mt * 16 + arow) * astride_b + (k0 + acol) * 2);
#pragma unroll
            for (int j = 0; j < 4; j++) {
                mma_bf16(acc[mt][j][0], acc[mt][j][1], acc[mt][j][2], acc[mt][j][3],
                         ah0, ah1, ah2, ah3, bh[j][0], bh[j][1]);
                mma_bf16(acc[mt][j][0], acc[mt][j][1], acc[mt][j][2], acc[mt][j][3],
                         ah0, ah1, ah2, ah3, bl[j][0], bl[j][1]);
                mma_bf16(acc[mt][j][0], acc[mt][j][1], acc[mt][j][2], acc[mt][j][3],
                         al0, al1, al2, al3, bh[j][0], bh[j][1]);
            }
        }
        __syncthreads();
    }

    // writeback with bias
    float* base = g_res + ((size_t)b * NROWS + orow0) * TOK + col0;
#pragma unroll
    for (int mt = 0; mt < MT; mt++) {
        const int r0 = mt * 16 + g;
#pragma unroll
        for (int j = 0; j < 4; j++) {
            const int c = n0 + j * 8 + tg * 2;
            float bv0 = __ldg(&bias[col0 + c]);
            float bv1 = __ldg(&bias[col0 + c + 1]);
            if (r0 < nvalid) {
                float2 v = make_float2(acc[mt][j][0] + bv0, acc[mt][j][1] + bv1);
                *(float2*)(base + (size_t)r0 * TOK + c) = v;
            }
            if (r0 + 8 < nvalid) {
                float2 v = make_float2(acc[mt][j][2] + bv0, acc[mt][j][3] + bv1);
                *(float2*)(base + (size_t)(r0 + 8) * TOK + c) = v;
            }
        }
    }
}

// ---------------------------------------------------------------------------
// Proj: grid (16 batches, 16 n-tiles of 256 cols), block 256 (8 warps).
// G1: rows 0-10 (A1 x W1), G2: rows 11-21 (A2 x W2), G3: rows 22-42 (tenc x Wt).
// ---------------------------------------------------------------------------
__global__ void __launch_bounds__(256)
k_proj(const float* __restrict__ memory,
       const int*   __restrict__ src_nodes,
       const int*   __restrict__ dst_nodes,
       const int*   __restrict__ src_nei,
       const int*   __restrict__ dst_nei,
       const float* __restrict__ timestamps,
       const float* __restrict__ se,
       const float* __restrict__ de,
       const float* __restrict__ b1,
       const float* __restrict__ b2,
       const float* __restrict__ bt,
       const float* __restrict__ w_time,
       const float* __restrict__ phase)
{
    extern __shared__ __align__(16) char sm[];
    char* Areg = sm;
    char* stg0 = sm + A_REGION_B;
    char* stg1 = stg0 + WSTG_B;

    const int b    = blockIdx.x;
    const int tile = blockIdx.y;
    const int col0 = tile * 256;
    const int tid  = threadIdx.x;

    // ---- stage A1/A2 hi/lo (16 rows x 176 cols each, pad rows/cols zero) ----
    for (int i = tid; i < 2 * 16 * 176; i += 256) {
        int m = i / (16 * 176);
        int r = (i / 176) & 15;
        int k = i % 176;
        float a = 0.f;
        if (r < 11 && k < 172) {
            int node;
            if (m == 0) node = (r == 0) ? src_nodes[b] : dst_nei[b * 10 + r - 1];
            else        node = (r == 0) ? dst_nodes[b] : src_nei[b * 10 + r - 1];
            a = memory[(size_t)node * MEM_DIM + k];
        }
        __nv_bfloat16 h = __float2bfloat16(a);
        __nv_bfloat16 l = __float2bfloat16(a - __bfloat162float(h));
        __nv_bfloat16* Ah = (__nv_bfloat16*)(Areg + m * 11776);
        __nv_bfloat16* Al = (__nv_bfloat16*)(Areg + m * 11776 + 5888);
        Ah[r * 184 + k] = h;
        Al[r * 184 + k] = l;
    }
    // (sync provided by first in-loop barrier of G1)

    const uint32_t A1h = s2u(Areg), A1l = s2u(Areg + 5888);
    const uint32_t A2h = s2u(Areg + 11776), A2l = s2u(Areg + 17664);

    run_gemm<1, 11>(stg0, stg1, A1h, A1l, 368, 0,   col0, b, 0,  11, b1, tid);
    run_gemm<1, 11>(stg0, stg1, A2h, A2l, 368, 176, col0, b, 11, 11, b2, tid);

    // ---- stage tenc hi/lo (32 rows x 112 cols; rows>=21, cols>=100 zero) ----
    __syncthreads();
    const float t0 = timestamps[b];
    for (int i = tid; i < 32 * 112; i += 256) {
        int r = i / 112;
        int k = i % 112;
        float v = 0.f;
        if (r < 21 && k < 100) {
            float delta;
            if (r == 0)      delta = 0.f;
            else if (r < 11) delta = t0 - se[b * 10 + r - 1];
            else             delta = t0 - de[b * 10 + r - 11];
            v = cosf(delta * w_time[k] + phase[k]);
        }
        __nv_bfloat16 h = __float2bfloat16(v);
        __nv_bfloat16 l = __float2bfloat16(v - __bfloat162float(h));
        ((__nv_bfloat16*)Areg)[r * 120 + k] = h;
        ((__nv_bfloat16*)(Areg + 7680))[r * 120 + k] = l;
    }

    const uint32_t Th = s2u(Areg), Tl = s2u(Areg + 7680);
    run_gemm<2, 7>(stg0, stg1, Th, Tl, 240, 352, col0, b, 22, 21, bt, tid);
}

// ---------------------------------------------------------------------------
// Scat (R9 proven): grid (16 b, 16 tiles of 256 cols, 25 runs), block 256.
// ---------------------------------------------------------------------------
__global__ void __launch_bounds__(256)
k_scat(float* __restrict__ out)
{
    const int b    = blockIdx.x;
    const int tile = blockIdx.y;
    const int z    = blockIdx.z;
    const int tid  = threadIdx.x;
    const int lane = tid & 63;
    const int sub  = tid >> 6;

    int t0, n, rS, rD, rT;
    if (z < 10)       { t0 = 15 + 21 * z;  n = 21; rS = 0;  rD = 12 + z; rT = 23 + z; }
    else if (z < 20)  { int q = z - 10; t0 = 239 + 21 * q; n = 21; rS = 11; rD = 1 + q; rT = 33 + q; }
    else if (z == 20) { t0 = 0;   n = 15; rS = 0;  rD = 11; rT = 22; }
    else if (z == 21) { t0 = 225; n = 14; rS = 11; rD = 11; rT = 22; }
    else              { t0 = 449 + 21 * (z - 22); n = 21; rS = 0; rD = 11; rT = 22; }

    const float4* gresv = (const float4*)g_res;
    const int vrow = TOK / 4;
    const size_t rbase = (size_t)b * NROWS * vrow + tile * 64 + lane;
    const float4 vs = __ldg(&gresv[rbase + (size_t)rS * vrow]);
    const float4 vd = __ldg(&gresv[rbase + (size_t)rD * vrow]);
    const float4 vt = __ldg(&gresv[rbase + (size_t)rT * vrow]);

    float4* outv = (float4*)out;
    const size_t T = (size_t)BATCH * LEN_TOK * vrow;
    const size_t obase = (size_t)(b * LEN_TOK) * vrow + tile * 64 + lane;

    if (z == 20) {
        for (int i = sub; i < n; i += 4) {
            const int t = t0 + i;
            const size_t o = obase + (size_t)t * vrow;
            __stcs(&outv[o],         vs);
            __stcs(&outv[o + T],     (t == 0) ? vd : vs);
            __stcs(&outv[o + 2 * T], vt);
        }
    } else {
        for (int i = sub; i < n; i += 4) {
            const size_t o = obase + (size_t)(t0 + i) * vrow;
            __stcs(&outv[o],         vs);
            __stcs(&outv[o + T],     vd);
            __stcs(&outv[o + 2 * T], vt);
        }
    }
}

// ---------------------------------------------------------------------------
extern "C" void kernel_launch(void* const* d_in, const int* in_sizes, int n_in,
                              void* d_out, int out_size)
{
    const float* memory      = (const float*)d_in[0];
    const int*   src_nodes   = (const int*)  d_in[1];
    const int*   dst_nodes   = (const int*)  d_in[2];
    const int*   src_nei     = (const int*)  d_in[3];
    const int*   dst_nei     = (const int*)  d_in[4];
    const float* timestamps  = (const float*)d_in[5];
    const float* se          = (const float*)d_in[6];
    const float* de          = (const float*)d_in[7];
    const float* W1          = (const float*)d_in[8];
    const float* b1          = (const float*)d_in[9];
    const float* W2          = (const float*)d_in[10];
    const float* b2          = (const float*)d_in[11];
    const float* Wt          = (const float*)d_in[12];
    const float* bt          = (const float*)d_in[13];
    const float* w_time      = (const float*)d_in[14];
    const float* phase       = (const float*)d_in[15];
    float* out = (float*)d_out;

    cudaFuncSetAttribute(k_proj, cudaFuncAttributeMaxDynamicSharedMemorySize, SMEMP_B);

    k_prep<<<(WROWS * TOK + 255) / 256, 256>>>(W1, W2, Wt);
    k_proj<<<dim3(BATCH, TOK / 256), 256, SMEMP_B>>>(memory, src_nodes, dst_nodes,
                                                     src_nei, dst_nei,
                                                     timestamps, se, de,
                                                     b1, b2, bt, w_time, phase);
    k_scat<<<dim3(BATCH, TOK / 256, 25), 256>>>(out);
}